// round 3
// baseline (speedup 1.0000x reference)
#include <cuda_runtime.h>
#include <math.h>

#define NANCH_MAX 196416
#define CMAX      80
#define CAP       4096
#define TOPK      1000
#define MAXD      100
#define NEGV      (-1e9f)
#define SCORE_T   0.05f

// ----------------------------- device scratch (static) -----------------------------
__device__ float4             g_boxes[NANCH_MAX];
__device__ float              g_lo[CMAX];
__device__ float              g_hi[CMAX];
__device__ unsigned           g_cntLo[CMAX];
__device__ int                g_done[CMAX];
__device__ unsigned           g_cnt8[CMAX * 8];
__device__ int                g_cnt[CMAX];
__device__ unsigned long long g_cand[CMAX * CAP];

// identical FP expression used by k_count and k_refine (forced fma → same result)
__device__ __forceinline__ float thr_k(float lo, float hi, int k) {
    return __fmaf_rn(hi - lo, (float)(k + 1) * (1.0f / 9.0f), lo);
}

// ----------------------------- init -----------------------------
__global__ void k_init(int C) {
    int t = blockIdx.x * blockDim.x + threadIdx.x;
    if (t < C) {
        g_lo[t]    = SCORE_T;
        g_hi[t]    = 1.0f;
        g_cntLo[t] = 0x7FFFFFFFu;
        g_done[t]  = 0;
        g_cnt[t]   = 0;
    }
    if (t < C * 8) g_cnt8[t] = 0;
}

// ----------------------------- box decode -----------------------------
__global__ void k_decode(const float* __restrict__ anch,
                         const float* __restrict__ reg,
                         int N, float side) {
    int i = blockIdx.x * blockDim.x + threadIdx.x;
    if (i >= N || i >= NANCH_MAX) return;
    float4 a = ((const float4*)anch)[i];
    float w  = a.z - a.x;
    float h  = a.w - a.y;
    float cx = a.x + 0.5f * w;
    float cy = a.y + 0.5f * h;
    float dx = reg[i]         * 0.1f;
    float dy = reg[N + i]     * 0.1f;
    float dw = reg[2 * N + i] * 0.2f;
    float dh = reg[3 * N + i] * 0.2f;
    float pcx = cx + dx * w;
    float pcy = cy + dy * h;
    float pw  = expf(dw) * w;
    float ph  = expf(dh) * h;
    float x1 = fmaxf(pcx - 0.5f * pw, 0.0f);
    float y1 = fmaxf(pcy - 0.5f * ph, 0.0f);
    float x2 = fminf(pcx + 0.5f * pw, side);
    float y2 = fminf(pcy + 0.5f * ph, side);
    g_boxes[i] = make_float4(x1, y1, x2, y2);
}

// ----------------------------- 8-threshold counting pass -----------------------------
__global__ void k_count(const float* __restrict__ cls, int N) {
    int c = blockIdx.y;
    if (g_done[c]) return;
    float lo = g_lo[c], hi = g_hi[c];
    float T[8];
#pragma unroll
    for (int k = 0; k < 8; k++) T[k] = thr_k(lo, hi, k);
    unsigned cnt[8];
#pragma unroll
    for (int k = 0; k < 8; k++) cnt[k] = 0u;

    const float*  base = cls + (size_t)c * N;
    const float4* p4   = (const float4*)base;
    int n4     = N >> 2;
    int stride = gridDim.x * blockDim.x;
    for (int i = blockIdx.x * blockDim.x + threadIdx.x; i < n4; i += stride) {
        float4 v = p4[i];
#pragma unroll
        for (int k = 0; k < 8; k++)
            cnt[k] += (unsigned)(v.x >= T[k]) + (unsigned)(v.y >= T[k]) +
                      (unsigned)(v.z >= T[k]) + (unsigned)(v.w >= T[k]);
    }
    for (int i = (n4 << 2) + blockIdx.x * blockDim.x + threadIdx.x; i < N; i += stride) {
        float v = base[i];
#pragma unroll
        for (int k = 0; k < 8; k++) cnt[k] += (unsigned)(v >= T[k]);
    }
#pragma unroll
    for (int k = 0; k < 8; k++) {
#pragma unroll
        for (int off = 16; off > 0; off >>= 1)
            cnt[k] += __shfl_down_sync(0xFFFFFFFFu, cnt[k], off);
    }
    if ((threadIdx.x & 31) == 0) {
#pragma unroll
        for (int k = 0; k < 8; k++) atomicAdd(&g_cnt8[c * 8 + k], cnt[k]);
    }
}

// ----------------------------- bracket refine -----------------------------
__global__ void k_refine(int C) {
    int c = threadIdx.x;
    if (c >= C) return;
    if (!g_done[c]) {
        unsigned cc[8];
#pragma unroll
        for (int k = 0; k < 8; k++) cc[k] = g_cnt8[c * 8 + k];
        float lo0 = g_lo[c], hi0 = g_hi[c];
        float nlo = lo0, nhi = hi0;
        unsigned cntLo = g_cntLo[c];
        if (cc[7] >= TOPK) {
            nlo = thr_k(lo0, hi0, 7);
            cntLo = cc[7];
        } else {
            int j = 0;
            while (j < 8 && cc[j] >= TOPK) j++;   // first with count < TOPK
            if (j > 0) { nlo = thr_k(lo0, hi0, j - 1); cntLo = cc[j - 1]; }
            nhi = thr_k(lo0, hi0, j);
        }
        g_lo[c] = nlo;
        g_hi[c] = nhi;
        g_cntLo[c] = cntLo;
        if (cntLo <= CAP) g_done[c] = 1;
    }
#pragma unroll
    for (int k = 0; k < 8; k++) g_cnt8[c * 8 + k] = 0;
}

// ----------------------------- candidate collection -----------------------------
__global__ void k_collect(const float* __restrict__ cls, int N) {
    int c = blockIdx.y;
    float lo = g_lo[c];
    const float*  base = cls + (size_t)c * N;
    const float4* p4   = (const float4*)base;
    int n4     = N >> 2;
    int stride = gridDim.x * blockDim.x;
    for (int i = blockIdx.x * blockDim.x + threadIdx.x; i < n4; i += stride) {
        float4 v = p4[i];
#pragma unroll
        for (int q = 0; q < 4; q++) {
            float s = (q == 0) ? v.x : (q == 1) ? v.y : (q == 2) ? v.z : v.w;
            if (s >= lo && s > SCORE_T) {
                int pos = atomicAdd(&g_cnt[c], 1);
                if (pos < CAP) {
                    unsigned idx = (unsigned)(i * 4 + q);
                    g_cand[c * CAP + pos] =
                        ((unsigned long long)__float_as_uint(s) << 32) |
                        (unsigned long long)(~idx);
                }
            }
        }
    }
    for (int i = (n4 << 2) + blockIdx.x * blockDim.x + threadIdx.x; i < N; i += stride) {
        float s = base[i];
        if (s >= lo && s > SCORE_T) {
            int pos = atomicAdd(&g_cnt[c], 1);
            if (pos < CAP)
                g_cand[c * CAP + pos] =
                    ((unsigned long long)__float_as_uint(s) << 32) |
                    (unsigned long long)(~(unsigned)i);
        }
    }
}

// ----------------------------- per-class sort + greedy NMS -----------------------------
__global__ __launch_bounds__(1024, 1)
void k_sortnms(float* __restrict__ out, int C) {
    __shared__ unsigned long long skey[CAP];   // 32 KB, reused as floats after sort
    __shared__ unsigned swk[32];
    __shared__ int s_sel;

    int c   = blockIdx.x;
    int tid = threadIdx.x;
    int m   = g_cnt[c];
    if (m > CAP) m = CAP;

    for (int i = tid; i < CAP; i += 1024)
        skey[i] = (i < m) ? g_cand[c * CAP + i] : 0ULL;
    __syncthreads();

    // bitonic sort, descending
    for (int k = 2; k <= CAP; k <<= 1) {
        for (int j = k >> 1; j > 0; j >>= 1) {
            for (int i = tid; i < CAP; i += 1024) {
                int ixj = i ^ j;
                if (ixj > i) {
                    unsigned long long a = skey[i], b = skey[ixj];
                    bool sw = ((i & k) == 0) ? (a < b) : (a > b);
                    if (sw) { skey[i] = b; skey[ixj] = a; }
                }
            }
            __syncthreads();
        }
    }

    // extract my candidate to registers, then reuse skey memory for float arrays
    unsigned long long key = skey[tid];
    __syncthreads();

    float* S      = (float*)skey;
    float* sx1    = S + 1024;
    float* sy1    = S + 2048;
    float* sx2    = S + 3072;
    float* sy2    = S + 4096;
    float* sarea  = S + 5120;

    bool alive = (tid < TOPK) && (tid < m);
    float  sc = NEGV;
    float4 b  = make_float4(0.0f, 0.0f, 0.0f, 0.0f);
    if (alive) {
        sc = __uint_as_float((unsigned)(key >> 32));
        unsigned idx = ~(unsigned)(key & 0xFFFFFFFFu);
        b = g_boxes[idx];
    }
    float myArea = (b.z - b.x) * (b.w - b.y);
    S[tid]     = sc;       // sscore
    sx1[tid]   = b.x;
    sy1[tid]   = b.y;
    sx2[tid]   = b.z;
    sy2[tid]   = b.w;
    sarea[tid] = myArea;
    __syncthreads();

    int lane = tid & 31, wid = tid >> 5;
    float mx1 = b.x, my1 = b.y, mx2 = b.z, my2 = b.w;

    float* os   = out;                 // scores  [C*MAXD]
    float* ocls = out + C * MAXD;      // classes [C*MAXD]
    float* ob   = out + 2 * C * MAXD;  // boxes   [C*MAXD, 4]

    for (int r = 0; r < MAXD; r++) {
        unsigned bal = __ballot_sync(0xFFFFFFFFu, alive);
        if (lane == 0) swk[wid] = bal;
        __syncthreads();
        if (tid == 0) {
            int sel = -1;
            for (int w = 0; w < 32; w++) {
                unsigned mm = swk[w];
                if (mm) { sel = w * 32 + __ffs(mm) - 1; break; }
            }
            s_sel = sel;
        }
        __syncthreads();
        int sel = s_sel;
        int slot = c * MAXD + r;
        if (sel >= 0) {
            float px1 = sx1[sel], py1 = sy1[sel];
            float px2 = sx2[sel], py2 = sy2[sel];
            float pa  = sarea[sel];
            if (tid == sel) {
                os[slot]   = sc;            // real score > 0.05 → always "valid"
                ocls[slot] = (float)c;
                float* bb = ob + slot * 4;
                bb[0] = px1; bb[1] = py1; bb[2] = px2; bb[3] = py2;
                alive = false;              // explicit self-kill (matches .at[i].set(NEG))
            } else if (alive) {
                float ix1 = fmaxf(px1, mx1), iy1 = fmaxf(py1, my1);
                float ix2 = fminf(px2, mx2), iy2 = fminf(py2, my2);
                float inter = fmaxf(ix2 - ix1, 0.0f) * fmaxf(iy2 - iy1, 0.0f);
                float iou = inter / (pa + myArea - inter + 1e-8f);
                if (iou > 0.5f) alive = false;
            }
        } else {
            // all-NEG round in reference → output masked to (0, -1, 0-box)
            if (tid == 0) {
                os[slot]   = 0.0f;
                ocls[slot] = -1.0f;
                float* bb = ob + slot * 4;
                bb[0] = 0.0f; bb[1] = 0.0f; bb[2] = 0.0f; bb[3] = 0.0f;
            }
        }
    }
}

// ----------------------------- host launcher -----------------------------
extern "C" void kernel_launch(void* const* d_in, const int* in_sizes, int n_in,
                              void* d_out, int out_size) {
    const float* cls  = (const float*)d_in[1];   // [1, C, N]
    const float* reg  = (const float*)d_in[2];   // [1, 4, N]
    const float* anch = (const float*)d_in[3];   // [N, 4]
    float* out = (float*)d_out;

    int N = in_sizes[3] / 4;
    int C = in_sizes[1] / N;
    if (C > CMAX) C = CMAX;

    // image is [1,3,H,W] with H==W
    int hw   = in_sizes[0] / 3;
    int side = (int)(sqrt((double)hw) + 0.5);

    k_init<<<1, 1024>>>(C);
    k_decode<<<(N + 255) / 256, 256>>>(anch, reg, N, (float)side);

    for (int r = 0; r < 3; r++) {
        k_count<<<dim3(8, C), 256>>>(cls, N);
        k_refine<<<1, 128>>>(C);
    }
    k_collect<<<dim3(8, C), 256>>>(cls, N);
    k_sortnms<<<C, 1024>>>(out, C);
}